// round 6
// baseline (speedup 1.0000x reference)
#include <cuda_runtime.h>

// DotProcessorBlock: feat = x*w + b (per row, N=256)
// out[b, k] = feat[k>>8] * feat[k&255] for k in [0, 32896)
// B=4096 rows, ~539 MB of pure f32 stores -> HBM-write-bound (~90% of spec).
// R6: persistent grid-stride kernel at exactly one full wave of CTAs
//     (148 SMs x 8 CTAs = 1184) to eliminate the 27.7-wave raggedness and
//     wave-transition overhead. Inner body = barrier-free R5 form.

#define N_FEAT 256
#define NUM_OUT 32896                 // N*(N+1)/2
#define OUT_VEC4 (NUM_OUT / 4)        // 8224 float4 per row
#define CHUNKS 8
#define CHUNK_V4 (OUT_VEC4 / CHUNKS)  // 1028 float4 per chunk = 4*256 + 4
#define NUM_UNITS (4096 * CHUNKS)     // 32768 work units
#define PERSIST_CTAS (148 * 8)        // one full wave

__global__ __launch_bounds__(256, 8)
void dot_outer_kernel(const float* __restrict__ x,
                      const float* __restrict__ w,
                      const float* __restrict__ bias,
                      float* __restrict__ out)
{
    const int tid = threadIdx.x;

    for (int unit = blockIdx.x; unit < NUM_UNITS; unit += PERSIST_CTAS) {
        const int row   = unit >> 3;            // / CHUNKS
        const int chunk = unit & (CHUNKS - 1);

        const int t0 = chunk * CHUNK_V4 + tid;
        const int j  = t0 & 63;                 // float4 column, invariant (stride 256; 1024%64==0)

        const float4* __restrict__ x4 = reinterpret_cast<const float4*>(x) + (size_t)row * (N_FEAT / 4);
        const float4* __restrict__ w4 = reinterpret_cast<const float4*>(w);
        const float4* __restrict__ b4 = reinterpret_cast<const float4*>(bias);

        // fj = feat[4j..4j+3] in registers (no smem, no barrier)
        const float4 xa = x4[j];
        const float4 wa = w4[j];
        const float4 ba = b4[j];
        float4 fj;
        fj.x = fmaf(xa.x, wa.x, ba.x);
        fj.y = fmaf(xa.y, wa.y, ba.y);
        fj.z = fmaf(xa.z, wa.z, ba.z);
        fj.w = fmaf(xa.w, wa.w, ba.w);

        const float* __restrict__ xr = x + (size_t)row * N_FEAT;
        float4* __restrict__ out4 = reinterpret_cast<float4*>(out) + (size_t)row * OUT_VEC4;

        #pragma unroll
        for (int it = 0; it < 4; ++it) {
            const int t = t0 + it * 256;
            const int i = t >> 6;               // fi index, near-uniform per warp
            const float fi = fmaf(xr[i], w[i], bias[i]);
            float4 v;
            v.x = fj.x * fi; v.y = fj.y * fi; v.z = fj.z * fi; v.w = fj.w * fi;
            __stcs(&out4[t], v);
        }
        if (tid < (CHUNK_V4 - 4 * 256)) {       // 4-element tail, threads 0..3
            const int t = t0 + 1024;
            const int i = t >> 6;
            const float fi = fmaf(xr[i], w[i], bias[i]);
            float4 v;
            v.x = fj.x * fi; v.y = fj.y * fi; v.z = fj.z * fi; v.w = fj.w * fi;
            __stcs(&out4[t], v);
        }
    }
}

extern "C" void kernel_launch(void* const* d_in, const int* in_sizes, int n_in,
                              void* d_out, int out_size)
{
    const float* x    = (const float*)d_in[0];
    const float* w    = (const float*)d_in[1];
    const float* bias = (const float*)d_in[2];
    float* out        = (float*)d_out;

    dot_outer_kernel<<<PERSIST_CTAS, 256>>>(x, w, bias, out);
}

// round 7
// speedup vs baseline: 1.2722x; 1.2722x over previous
#include <cuda_runtime.h>

// DotProcessorBlock: feat = x*w + b (per row, N=256)
// out[b, k] = feat[k>>8] * feat[k&255] for k in [0, 32896)
// B=4096 rows, ~539 MB of pure f32 stores -> HBM-write-bound (~90% of spec).
// R7: barrier-free body (R5) at CHUNKS=16. Discriminates R4's regression:
//     if it was the collective prologue barrier (now gone), the finer quantum
//     harvests the remaining drain tail; if it was CTA-transition cost, revert.

#define N_FEAT 256
#define NUM_OUT 32896                 // N*(N+1)/2
#define OUT_VEC4 (NUM_OUT / 4)        // 8224 float4 per row
#define CHUNKS 16
#define CHUNK_V4 (OUT_VEC4 / CHUNKS)  // 514 float4 per chunk = 2*256 + 2

__global__ __launch_bounds__(256, 8)
void dot_outer_kernel(const float* __restrict__ x,
                      const float* __restrict__ w,
                      const float* __restrict__ bias,
                      float* __restrict__ out)
{
    const int row   = blockIdx.x >> 4;          // / CHUNKS
    const int chunk = blockIdx.x & (CHUNKS - 1);
    const int tid   = threadIdx.x;

    const int t0 = chunk * CHUNK_V4 + tid;
    const int j  = t0 & 63;                     // float4 column, invariant under t += 256
                                                // (tail +512: 512 % 64 == 0, still invariant)

    const float4* __restrict__ x4 = reinterpret_cast<const float4*>(x) + (size_t)row * (N_FEAT / 4);
    const float4* __restrict__ w4 = reinterpret_cast<const float4*>(w);
    const float4* __restrict__ b4 = reinterpret_cast<const float4*>(bias);

    // fj = feat[4j..4j+3] in registers (no smem, no barrier, warp-private latency)
    const float4 xa = x4[j];
    const float4 wa = w4[j];
    const float4 ba = b4[j];
    float4 fj;
    fj.x = fmaf(xa.x, wa.x, ba.x);
    fj.y = fmaf(xa.y, wa.y, ba.y);
    fj.z = fmaf(xa.z, wa.z, ba.z);
    fj.w = fmaf(xa.w, wa.w, ba.w);

    const float* __restrict__ xr = x + (size_t)row * N_FEAT;
    float4* __restrict__ out4 = reinterpret_cast<float4*>(out) + (size_t)row * OUT_VEC4;

    // Iteration 0 and 1 (always in range: CHUNK_V4 = 2*256 + 2)
    {
        const int i = t0 >> 6;                  // fi index, near-uniform per warp
        const float fi = fmaf(xr[i], w[i], bias[i]);
        float4 v = { fj.x * fi, fj.y * fi, fj.z * fi, fj.w * fi };
        __stcs(&out4[t0], v);
    }
    {
        const int t1 = t0 + 256;
        const int i = t1 >> 6;
        const float fi = fmaf(xr[i], w[i], bias[i]);
        float4 v = { fj.x * fi, fj.y * fi, fj.z * fi, fj.w * fi };
        __stcs(&out4[t1], v);
    }
    // 2-element tail (threads 0..1); fj index unchanged since 512 % 64 == 0
    if (tid < (CHUNK_V4 - 2 * 256)) {
        const int t2 = t0 + 512;
        const int i = t2 >> 6;
        const float fi = fmaf(xr[i], w[i], bias[i]);
        float4 v = { fj.x * fi, fj.y * fi, fj.z * fi, fj.w * fi };
        __stcs(&out4[t2], v);
    }
}

extern "C" void kernel_launch(void* const* d_in, const int* in_sizes, int n_in,
                              void* d_out, int out_size)
{
    const float* x    = (const float*)d_in[0];
    const float* w    = (const float*)d_in[1];
    const float* bias = (const float*)d_in[2];
    float* out        = (float*)d_out;

    const int B = in_sizes[0] / N_FEAT;   // 4096
    dot_outer_kernel<<<B * CHUNKS, 256>>>(x, w, bias, out);
}